// round 3
// baseline (speedup 1.0000x reference)
#include <cuda_runtime.h>
#include <cuda_bf16.h>

// ConLoss: supervised contrastive loss.
//   Fn = row-normalized features; S = Fn Fn^T (symmetric, computed triangularly)
//   neg_i = sum_{j: cls_j != cls_i} exp(S_ij/TAU)
//   loss  = [ sum_i (1/P_i) sum_{j!=i, cls_j==cls_i} ( log(exp(S_ij/TAU)+neg_i) - S_ij/TAU ) ] / sum_i P_i
// Fully deterministic: no floating-point atomics anywhere.

#define CN 4096
#define CD 512
#define BM 128
#define BN 128
#define BK 16
#define NT (CN / BM)                 // 32 tiles per dim
#define NPAIRS (NT * (NT + 1) / 2)   // 528 triangular tile pairs

#define TAUINV 10.0f
#define EXP2SCALE 14.4269504088896340736f  // (1/TAU) * log2(e)

// ---- scratch (device globals; no allocation) ----
__device__ float g_Fn[CN * CD];       // 8 MB  normalized features
__device__ int   g_cls[CN];           // class labels as int32
__device__ float g_negpart[NT * CN];  // 512 KB per-(otherTile,row) exp-sum partials
__device__ float g_rowloss[CN];
__device__ int   g_rowP[CN];
__device__ int   g_is64;              // 1 if targets buffer is int64, else 0

// ============ kernel 0: detect targets dtype (int32 vs int64) ============
// Reads ONLY the first CN int32 words — safe under both dtypes (buffer is
// >= 4*CN bytes either way). Little-endian int64 values in [0,100) make every
// odd int32 word zero; genuine int32 labels essentially never do.
__global__ void k0_detect(const int* __restrict__ t32) {
    __shared__ int bad;
    if (threadIdx.x == 0) bad = 0;
    __syncthreads();
    for (int idx = 1 + 2 * threadIdx.x; idx < CN; idx += 2 * blockDim.x)
        if (t32[idx] != 0) bad = 1;   // benign race: only ever set to 1
    __syncthreads();
    if (threadIdx.x == 0) g_is64 = bad ? 0 : 1;
}

// ============ kernel 1: normalize rows, cast labels ============
__global__ void k1_normalize(const float* __restrict__ F,
                             const int* __restrict__ t32) {
    int row = blockIdx.x;
    int tid = threadIdx.x;            // 128 threads, D/4 = 128 float4
    const float4* fr = (const float4*)(F + (size_t)row * CD);
    float4 x = fr[tid];
    float ss = x.x * x.x + x.y * x.y + x.z * x.z + x.w * x.w;
    #pragma unroll
    for (int o = 16; o > 0; o >>= 1)
        ss += __shfl_xor_sync(0xffffffffu, ss, o);
    __shared__ float ws[4];
    __shared__ float s_inv;
    int wid = tid >> 5, lane = tid & 31;
    if (lane == 0) ws[wid] = ss;
    __syncthreads();
    if (tid == 0) {
        float t = ws[0] + ws[1] + ws[2] + ws[3];
        s_inv = (t > 0.0f) ? rsqrtf(t) : 0.0f;
        g_cls[row] = g_is64 ? t32[2 * row] : t32[row];
    }
    __syncthreads();
    float inv = s_inv;
    float4 o = make_float4(x.x * inv, x.y * inv, x.z * inv, x.w * inv);
    ((float4*)(g_Fn + (size_t)row * CD))[tid] = o;
}

// ============ kernel 2: triangular fused Gram + exp + neg partials ============
__global__ __launch_bounds__(256, 2) void k2_gram() {
    int b = blockIdx.x;
    // decode b = jT*(jT+1)/2 + iT, iT <= jT
    int jT = (int)((sqrtf(8.0f * b + 1.0f) - 1.0f) * 0.5f);
    while ((jT + 1) * (jT + 2) / 2 <= b) jT++;
    while (jT * (jT + 1) / 2 > b) jT--;
    int iT = b - jT * (jT + 1) / 2;
    int i0 = iT * BM, j0 = jT * BN;
    bool diag = (iT == jT);

    __shared__ float As[BK][BM];
    __shared__ float Bs[BK][BN];
    __shared__ float sMat[16][BM];
    __shared__ int clsI[BM], clsJ[BN];

    int tid = threadIdx.x;
    if (tid < BM) {
        clsI[tid] = g_cls[i0 + tid];
        clsJ[tid] = g_cls[j0 + tid];
    }

    int tm = tid >> 4, tn = tid & 15;           // 16x16 thread grid, 8x8 per thread
    float acc[8][8];
    #pragma unroll
    for (int r = 0; r < 8; r++)
        #pragma unroll
        for (int c = 0; c < 8; c++) acc[r][c] = 0.0f;

    int ldRow = tid >> 2;                        // 0..63
    int ldK4 = (tid & 3) * 4;                    // 0,4,8,12
    const float* Aptr = g_Fn + (size_t)(i0 + ldRow) * CD + ldK4;
    const float* Bptr = g_Fn + (size_t)(j0 + ldRow) * CD + ldK4;

    for (int k0 = 0; k0 < CD; k0 += BK) {
        float4 a0 = *(const float4*)(Aptr + k0);
        float4 a1 = *(const float4*)(Aptr + 64 * CD + k0);
        float4 b0 = *(const float4*)(Bptr + k0);
        float4 b1 = *(const float4*)(Bptr + 64 * CD + k0);
        __syncthreads();
        As[ldK4 + 0][ldRow] = a0.x; As[ldK4 + 1][ldRow] = a0.y;
        As[ldK4 + 2][ldRow] = a0.z; As[ldK4 + 3][ldRow] = a0.w;
        As[ldK4 + 0][ldRow + 64] = a1.x; As[ldK4 + 1][ldRow + 64] = a1.y;
        As[ldK4 + 2][ldRow + 64] = a1.z; As[ldK4 + 3][ldRow + 64] = a1.w;
        Bs[ldK4 + 0][ldRow] = b0.x; Bs[ldK4 + 1][ldRow] = b0.y;
        Bs[ldK4 + 2][ldRow] = b0.z; Bs[ldK4 + 3][ldRow] = b0.w;
        Bs[ldK4 + 0][ldRow + 64] = b1.x; Bs[ldK4 + 1][ldRow + 64] = b1.y;
        Bs[ldK4 + 2][ldRow + 64] = b1.z; Bs[ldK4 + 3][ldRow + 64] = b1.w;
        __syncthreads();
        #pragma unroll
        for (int k = 0; k < BK; k++) {
            float av[8], bv[8];
            *(float4*)&av[0] = *(const float4*)&As[k][tm * 8];
            *(float4*)&av[4] = *(const float4*)&As[k][tm * 8 + 4];
            *(float4*)&bv[0] = *(const float4*)&Bs[k][tn * 8];
            *(float4*)&bv[4] = *(const float4*)&Bs[k][tn * 8 + 4];
            #pragma unroll
            for (int r = 0; r < 8; r++)
                #pragma unroll
                for (int c = 0; c < 8; c++)
                    acc[r][c] += av[r] * bv[c];
        }
    }

    // epilogue: exp of negatives (class differs; diagonal auto-excluded since
    // i==j implies same class), accumulate per-row and per-col
    float rowAcc[8], colAcc[8];
    #pragma unroll
    for (int r = 0; r < 8; r++) { rowAcc[r] = 0.0f; colAcc[r] = 0.0f; }
    #pragma unroll
    for (int r = 0; r < 8; r++) {
        int ci = clsI[tm * 8 + r];
        #pragma unroll
        for (int c = 0; c < 8; c++) {
            int cj = clsJ[tn * 8 + c];
            float e = exp2f(acc[r][c] * EXP2SCALE);
            if (ci != cj) { rowAcc[r] += e; colAcc[c] += e; }
        }
    }

    // deterministic block reduction via staging matrix (fixed-order 16-term sums)
    __syncthreads();
    #pragma unroll
    for (int r = 0; r < 8; r++) sMat[tn][tm * 8 + r] = rowAcc[r];
    __syncthreads();
    if (tid < BM) {
        float s = 0.0f;
        #pragma unroll
        for (int t = 0; t < 16; t++) s += sMat[t][tid];
        g_negpart[(size_t)jT * CN + i0 + tid] = s;   // exactly one writer per slot
    }
    __syncthreads();
    if (!diag) {
        #pragma unroll
        for (int c = 0; c < 8; c++) sMat[tm][tn * 8 + c] = colAcc[c];
        __syncthreads();
        if (tid < BN) {
            float s = 0.0f;
            #pragma unroll
            for (int t = 0; t < 16; t++) s += sMat[t][tid];
            g_negpart[(size_t)iT * CN + j0 + tid] = s;
        }
    }
}

// ============ kernel 3: per-row positive-pair loss (recompute dots) ============
__global__ void k3_rowloss() {
    int i = blockIdx.x;
    int tid = threadIdx.x;             // 128 threads = 4 warps
    int w = tid >> 5, lane = tid & 31;

    __shared__ float sh_neg;
    __shared__ float sh_sum[4];
    __shared__ int sh_P[4];

    // neg_i = fixed-order-tree sum of 32 partials (warp 0)
    if (w == 0) {
        float v = g_negpart[(size_t)lane * CN + i];
        #pragma unroll
        for (int o = 16; o > 0; o >>= 1)
            v += __shfl_xor_sync(0xffffffffu, v, o);
        if (lane == 0) sh_neg = v;
    }
    __syncthreads();
    float neg = sh_neg;

    int ci = g_cls[i];

    // this row's features in registers (lane-strided float4)
    float4 ri[4];
    const float4* pi = (const float4*)(g_Fn + (size_t)i * CD);
    #pragma unroll
    for (int q = 0; q < 4; q++) ri[q] = pi[lane + 32 * q];

    float wsum = 0.0f;
    int wP = 0;
    int jbeg = w * (CN / 4), jend = jbeg + (CN / 4);
    for (int base = jbeg; base < jend; base += 32) {
        int j = base + lane;
        int cj = g_cls[j];
        bool same = (cj == ci);
        wP += __popc(__ballot_sync(0xffffffffu, same));
        unsigned m = __ballot_sync(0xffffffffu, same && (j != i));
        while (m) {
            int jj = base + (__ffs(m) - 1);
            m &= m - 1;
            const float4* pj = (const float4*)(g_Fn + (size_t)jj * CD);
            float d = 0.0f;
            #pragma unroll
            for (int q = 0; q < 4; q++) {
                float4 vj = pj[lane + 32 * q];
                d += ri[q].x * vj.x + ri[q].y * vj.y +
                     ri[q].z * vj.z + ri[q].w * vj.w;
            }
            #pragma unroll
            for (int o = 16; o > 0; o >>= 1)
                d += __shfl_xor_sync(0xffffffffu, d, o);
            float l = d * TAUINV;
            wsum += logf(expf(l) + neg) - l;    // identical on all lanes
        }
    }
    if (lane == 0) { sh_sum[w] = wsum; sh_P[w] = wP; }
    __syncthreads();
    if (tid == 0) {
        float tot = sh_sum[0] + sh_sum[1] + sh_sum[2] + sh_sum[3];
        int P = sh_P[0] + sh_P[1] + sh_P[2] + sh_P[3];   // includes self
        g_rowloss[i] = tot / (float)P;
        g_rowP[i] = P;
    }
}

// ============ kernel 4: final fixed-order reduction ============
__global__ void k4_final(float* __restrict__ out) {
    __shared__ float sl[256];
    __shared__ int sp[256];
    int tid = threadIdx.x;
    float s = 0.0f;
    int p = 0;
    for (int i = tid; i < CN; i += 256) { s += g_rowloss[i]; p += g_rowP[i]; }
    sl[tid] = s; sp[tid] = p;
    __syncthreads();
    for (int st = 128; st > 0; st >>= 1) {
        if (tid < st) { sl[tid] += sl[tid + st]; sp[tid] += sp[tid + st]; }
        __syncthreads();
    }
    if (tid == 0) out[0] = sl[0] / (float)sp[0];
}

extern "C" void kernel_launch(void* const* d_in, const int* in_sizes, int n_in,
                              void* d_out, int out_size) {
    const float* F = (const float*)d_in[0];
    const int* T32 = (const int*)d_in[1];
    float* out = (float*)d_out;
    (void)in_sizes; (void)n_in; (void)out_size;

    k0_detect<<<1, 256>>>(T32);
    k1_normalize<<<CN, 128>>>(F, T32);
    k2_gram<<<NPAIRS, 256>>>();
    k3_rowloss<<<CN, 128>>>();
    k4_final<<<1, 256>>>(out);
}

// round 5
// speedup vs baseline: 2.3634x; 2.3634x over previous
#include <cuda_runtime.h>
#include <cstdint>

// ConLoss via mma.sync tf32 (compute_103-safe; no tcgen05).
//   k0: target dtype detect   k1: row normalize
//   k2: triangular 128x128 tf32 mma.sync tiles -> exp tile to g_S + neg partials
//   k3: per-row positive gather from g_S + log terms
//   k4: final reduction
// Deterministic: no fp atomics; fixed-order reductions everywhere.

#define CN 4096
#define CD 512
#define BM 128
#define NT (CN / BM)                  // 32
#define NPAIRS (NT * (NT + 1) / 2)    // 528
#define KC 64
#define NCHUNK (CD / KC)              // 8
#define KSTRIDE 68                    // padded smem row stride (floats)
#define EXP2SCALE 14.4269504088896340736f   // (1/TAU)*log2(e)

// ---- scratch ----
__device__ float g_Fn[CN * CD];                  // 8 MB normalized features
__device__ int   g_cls[CN];
__device__ float g_negpart[NT * CN];
__device__ float g_S[(size_t)NPAIRS * BM * BM];  // 34.6 MB exp(S/tau) tiles
__device__ float g_rowloss[CN];
__device__ int   g_rowP[CN];
__device__ int   g_is64;

// ============ kernel 0: detect targets dtype (int32 vs int64) ============
__global__ void k0_detect(const int* __restrict__ t32) {
    __shared__ int bad;
    if (threadIdx.x == 0) bad = 0;
    __syncthreads();
    for (int idx = 1 + 2 * threadIdx.x; idx < CN; idx += 2 * blockDim.x)
        if (t32[idx] != 0) bad = 1;
    __syncthreads();
    if (threadIdx.x == 0) g_is64 = bad ? 0 : 1;
}

// ============ kernel 1: normalize rows, cast labels ============
__global__ void k1_normalize(const float* __restrict__ F,
                             const int* __restrict__ t32) {
    int row = blockIdx.x;
    int tid = threadIdx.x;  // 128
    const float4* fr = (const float4*)(F + (size_t)row * CD);
    float4 x = fr[tid];
    float ss = x.x * x.x + x.y * x.y + x.z * x.z + x.w * x.w;
    #pragma unroll
    for (int o = 16; o > 0; o >>= 1) ss += __shfl_xor_sync(0xffffffffu, ss, o);
    __shared__ float ws[4];
    __shared__ float s_inv;
    int wid = tid >> 5, lane = tid & 31;
    if (lane == 0) ws[wid] = ss;
    __syncthreads();
    if (tid == 0) {
        float t = ws[0] + ws[1] + ws[2] + ws[3];
        s_inv = (t > 0.0f) ? rsqrtf(t) : 0.0f;
        g_cls[row] = g_is64 ? t32[2 * row] : t32[row];
    }
    __syncthreads();
    float inv = s_inv;
    ((float4*)(g_Fn + (size_t)row * CD))[tid] =
        make_float4(x.x * inv, x.y * inv, x.z * inv, x.w * inv);
}

// ============ kernel 2: triangular Gram via mma.sync tf32 ============
// smem: As[128][68] | Bs[128][68] | clsI[128] clsJ[128] | sMatR[2][128] | sMatC[4][128]
#define SM_FLOATS (2 * 128 * KSTRIDE + 256 + 256 + 512)
#define SMEMSZ (SM_FLOATS * 4)

__global__ __launch_bounds__(256, 2) void k2_gram_mma() {
    extern __shared__ float smem[];
    float* As = smem;
    float* Bs = smem + 128 * KSTRIDE;
    int* clsI = (int*)(smem + 2 * 128 * KSTRIDE);
    int* clsJ = clsI + 128;
    float* sMatR = (float*)(clsJ + 128);   // [2][128]
    float* sMatC = sMatR + 256;            // [4][128]

    int tid = threadIdx.x, wid = tid >> 5, lane = tid & 31;
    int b = blockIdx.x;
    int jT = (int)((sqrtf(8.0f * b + 1.0f) - 1.0f) * 0.5f);
    while ((jT + 1) * (jT + 2) / 2 <= b) jT++;
    while (jT * (jT + 1) / 2 > b) jT--;
    int iT = b - jT * (jT + 1) / 2;
    int i0 = iT * BM, j0 = jT * BM;
    bool diag = (iT == jT);

    if (tid < 128) {
        clsI[tid] = g_cls[i0 + tid];
        clsJ[tid] = g_cls[j0 + tid];
    }

    int wm = wid & 3, wn = wid >> 2;        // 4 x 2 warp grid
    int mrow0 = wm * 32, ncol0 = wn * 64;   // warp tile 32x64

    float acc[2][8][4];
    #pragma unroll
    for (int mf = 0; mf < 2; mf++)
        #pragma unroll
        for (int nf = 0; nf < 8; nf++)
            #pragma unroll
            for (int q = 0; q < 4; q++) acc[mf][nf][q] = 0.0f;

    // loader mapping: 8 threads cover 128B of one row; 2 halves (A/B)
    int half = tid >> 7, t = tid & 127;
    int lgrp = t >> 3;                      // 16 row groups
    int lc4 = t & 7;                        // float4 idx 0..7 (+8 second pass)
    const float* gsrc = g_Fn + (size_t)(half ? j0 : i0) * CD;
    float* sdst = half ? Bs : As;

    for (int c = 0; c < NCHUNK; c++) {
        int k0 = c * KC;
        __syncthreads();
        #pragma unroll
        for (int it = 0; it < 8; it++) {
            int row = lgrp + it * 16;
            #pragma unroll
            for (int h = 0; h < 2; h++) {
                int c4 = lc4 + h * 8;
                float4 v = *(const float4*)(gsrc + (size_t)row * CD + k0 + c4 * 4);
                uint32_t rx, ry, rz, rw;
                asm("cvt.rna.tf32.f32 %0, %1;" : "=r"(rx) : "f"(v.x));
                asm("cvt.rna.tf32.f32 %0, %1;" : "=r"(ry) : "f"(v.y));
                asm("cvt.rna.tf32.f32 %0, %1;" : "=r"(rz) : "f"(v.z));
                asm("cvt.rna.tf32.f32 %0, %1;" : "=r"(rw) : "f"(v.w));
                uint32_t* d = (uint32_t*)(sdst + row * KSTRIDE + c4 * 4);
                d[0] = rx; d[1] = ry; d[2] = rz; d[3] = rw;
            }
        }
        __syncthreads();
        #pragma unroll
        for (int kk = 0; kk < KC; kk += 8) {
            uint32_t a[2][4];
            int ar = mrow0 + (lane >> 2);
            int ak = kk + (lane & 3);
            #pragma unroll
            for (int mf = 0; mf < 2; mf++) {
                int r = ar + mf * 16;
                a[mf][0] = *(const uint32_t*)(As + r * KSTRIDE + ak);
                a[mf][1] = *(const uint32_t*)(As + (r + 8) * KSTRIDE + ak);
                a[mf][2] = *(const uint32_t*)(As + r * KSTRIDE + ak + 4);
                a[mf][3] = *(const uint32_t*)(As + (r + 8) * KSTRIDE + ak + 4);
            }
            #pragma unroll
            for (int nf = 0; nf < 8; nf++) {
                int n = ncol0 + nf * 8 + (lane >> 2);
                uint32_t b0 = *(const uint32_t*)(Bs + n * KSTRIDE + kk + (lane & 3));
                uint32_t b1 = *(const uint32_t*)(Bs + n * KSTRIDE + kk + (lane & 3) + 4);
                #pragma unroll
                for (int mf = 0; mf < 2; mf++) {
                    asm volatile(
                        "mma.sync.aligned.m16n8k8.row.col.f32.tf32.tf32.f32 "
                        "{%0,%1,%2,%3}, {%4,%5,%6,%7}, {%8,%9}, {%0,%1,%2,%3};"
                        : "+f"(acc[mf][nf][0]), "+f"(acc[mf][nf][1]),
                          "+f"(acc[mf][nf][2]), "+f"(acc[mf][nf][3])
                        : "r"(a[mf][0]), "r"(a[mf][1]), "r"(a[mf][2]), "r"(a[mf][3]),
                          "r"(b0), "r"(b1));
                }
            }
        }
    }

    // ---- epilogue: exp, mask, deterministic row/col partials, g_S store ----
    // lane's frag (mf,nf): rows r=mrow0+mf*16+(lane>>2), r+8; cols c=ncol0+nf*8+(lane&3)*2, c+1
    size_t pairBase = (size_t)b * (BM * BM);
    float rowP[2][2] = {{0, 0}, {0, 0}};    // [mf][row/row+8]
    float colP[8][2];                       // [nf][c/c+1]
    #pragma unroll
    for (int nf = 0; nf < 8; nf++) { colP[nf][0] = 0.0f; colP[nf][1] = 0.0f; }

    int rr = mrow0 + (lane >> 2);
    int cc0 = ncol0 + (lane & 3) * 2;
    #pragma unroll
    for (int mf = 0; mf < 2; mf++) {
        int r = rr + mf * 16;
        int ci0 = clsI[r], ci1 = clsI[r + 8];
        #pragma unroll
        for (int nf = 0; nf < 8; nf++) {
            int col = cc0 + nf * 8;
            int cj0 = clsJ[col], cj1 = clsJ[col + 1];
            float e00 = exp2f(acc[mf][nf][0] * EXP2SCALE);
            float e01 = exp2f(acc[mf][nf][1] * EXP2SCALE);
            float e10 = exp2f(acc[mf][nf][2] * EXP2SCALE);
            float e11 = exp2f(acc[mf][nf][3] * EXP2SCALE);
            *(float2*)(g_S + pairBase + (size_t)r * BM + col) = make_float2(e00, e01);
            *(float2*)(g_S + pairBase + (size_t)(r + 8) * BM + col) = make_float2(e10, e11);
            float m00 = (ci0 != cj0) ? e00 : 0.0f;
            float m01 = (ci0 != cj1) ? e01 : 0.0f;
            float m10 = (ci1 != cj0) ? e10 : 0.0f;
            float m11 = (ci1 != cj1) ? e11 : 0.0f;
            rowP[mf][0] += m00 + m01;
            rowP[mf][1] += m10 + m11;
            colP[nf][0] += m00 + m10;
            colP[nf][1] += m01 + m11;
        }
    }
    // row partials: reduce over lanes sharing a row (lane&3)
    #pragma unroll
    for (int mf = 0; mf < 2; mf++)
        #pragma unroll
        for (int h = 0; h < 2; h++) {
            float v = rowP[mf][h];
            v += __shfl_xor_sync(0xffffffffu, v, 1);
            v += __shfl_xor_sync(0xffffffffu, v, 2);
            rowP[mf][h] = v;
        }
    if ((lane & 3) == 0) {
        #pragma unroll
        for (int mf = 0; mf < 2; mf++) {
            int r = rr + mf * 16;
            sMatR[wn * 128 + r] = rowP[mf][0];
            sMatR[wn * 128 + r + 8] = rowP[mf][1];
        }
    }
    // col partials: reduce over lanes sharing a col (lane>>2)
    #pragma unroll
    for (int nf = 0; nf < 8; nf++)
        #pragma unroll
        for (int h = 0; h < 2; h++) {
            float v = colP[nf][h];
            v += __shfl_xor_sync(0xffffffffu, v, 4);
            v += __shfl_xor_sync(0xffffffffu, v, 8);
            v += __shfl_xor_sync(0xffffffffu, v, 16);
            colP[nf][h] = v;
        }
    if (lane < 4) {
        #pragma unroll
        for (int nf = 0; nf < 8; nf++) {
            int col = ncol0 + nf * 8 + lane * 2;
            sMatC[wm * 128 + col] = colP[nf][0];
            sMatC[wm * 128 + col + 1] = colP[nf][1];
        }
    }
    __syncthreads();
    if (tid < 128) {
        g_negpart[(size_t)jT * CN + i0 + tid] = sMatR[tid] + sMatR[128 + tid];
        if (!diag)
            g_negpart[(size_t)iT * CN + j0 + tid] =
                sMatC[tid] + sMatC[128 + tid] + sMatC[256 + tid] + sMatC[384 + tid];
    }
}

// ============ kernel 3: per-row positive gather ============
__global__ __launch_bounds__(256) void k3_rowloss() {
    __shared__ int sCls[CN];               // 16 KB
    int tid = threadIdx.x, wid = tid >> 5, lane = tid & 31;
    for (int t = tid; t < CN; t += 256) sCls[t] = g_cls[t];
    __syncthreads();
    int row = blockIdx.x * 8 + wid;

    float v = g_negpart[(size_t)lane * CN + row];
    #pragma unroll
    for (int o = 16; o > 0; o >>= 1) v += __shfl_xor_sync(0xffffffffu, v, o);
    float neg = v;

    int ci = sCls[row];
    int ti = row >> 7, ri = row & 127;
    float sum = 0.0f;
    int P = 0;
    for (int jb = 0; jb < CN; jb += 32) {
        int j = jb + lane;
        int cj = sCls[j];
        if (cj == ci) {
            P++;
            if (j != row) {
                int tj = j >> 7, rj = j & 127;
                size_t idx = (ti <= tj)
                    ? ((size_t)(tj * (tj + 1) / 2 + ti)) * 16384 + (size_t)ri * 128 + rj
                    : ((size_t)(ti * (ti + 1) / 2 + tj)) * 16384 + (size_t)rj * 128 + ri;
                float e = g_S[idx];
                sum += logf(e + neg) - logf(e);
            }
        }
    }
    #pragma unroll
    for (int o = 16; o > 0; o >>= 1) {
        sum += __shfl_xor_sync(0xffffffffu, sum, o);
        P   += __shfl_xor_sync(0xffffffffu, P, o);
    }
    if (lane == 0) { g_rowloss[row] = sum / (float)P; g_rowP[row] = P; }
}

// ============ kernel 4: final fixed-order reduction ============
__global__ void k4_final(float* __restrict__ out) {
    __shared__ float sl[256];
    __shared__ int sp[256];
    int tid = threadIdx.x;
    float s = 0.0f; int p = 0;
    for (int i = tid; i < CN; i += 256) { s += g_rowloss[i]; p += g_rowP[i]; }
    sl[tid] = s; sp[tid] = p;
    __syncthreads();
    for (int st = 128; st > 0; st >>= 1) {
        if (tid < st) { sl[tid] += sl[tid + st]; sp[tid] += sp[tid + st]; }
        __syncthreads();
    }
    if (tid == 0) out[0] = sl[0] / (float)sp[0];
}

extern "C" void kernel_launch(void* const* d_in, const int* in_sizes, int n_in,
                              void* d_out, int out_size) {
    const float* F = (const float*)d_in[0];
    const int* T32 = (const int*)d_in[1];
    float* out = (float*)d_out;
    (void)in_sizes; (void)n_in; (void)out_size;

    cudaFuncSetAttribute(k2_gram_mma, cudaFuncAttributeMaxDynamicSharedMemorySize, SMEMSZ);

    k0_detect<<<1, 256>>>(T32);
    k1_normalize<<<CN, 128>>>(F, T32);
    k2_gram_mma<<<NPAIRS, 256, SMEMSZ>>>();
    k3_rowloss<<<CN / 8, 256>>>();
    k4_final<<<1, 256>>>(out);
}